// round 4
// baseline (speedup 1.0000x reference)
#include <cuda_runtime.h>
#include <stdint.h>

// Problem constants
#define TT   384      // num_thetas (= n1 = n2)
#define NN   384      // points per space
#define RR   384      // resolution
#define D1   128
#define D2   32
#define SZ1  (D1*TT)  // 49152
#define SZ2  (D2*TT)  // 12288

// Scratch (static device globals; no allocation allowed)
__device__ float g_v1[SZ1];
__device__ float g_v2[SZ2];
__device__ float g_nh1[TT*NN];   // transposed: [t][n]
__device__ float g_nh2[TT*NN];
__device__ float g_loss;
__device__ unsigned int g_done = 0;

// ---------------------------------------------------------------------------
// Threefry2x32, key = (0, 42), partitionable layout: bits(i) = o0^o1,
// counter = (0, i)
// ---------------------------------------------------------------------------
__device__ __forceinline__ uint32_t rotl32(uint32_t x, int d) {
    return (x << d) | (x >> (32 - d));
}

__device__ __forceinline__ void threefry_0_42(uint32_t x0, uint32_t x1,
                                              uint32_t& o0, uint32_t& o1) {
    const uint32_t ks0 = 0u;
    const uint32_t ks1 = 42u;
    const uint32_t ks2 = 0u ^ 42u ^ 0x1BD11BDAu;
    x0 += ks0; x1 += ks1;
#define TF_R4(a,b,c,d)                               \
    x0 += x1; x1 = rotl32(x1,(a)); x1 ^= x0;          \
    x0 += x1; x1 = rotl32(x1,(b)); x1 ^= x0;          \
    x0 += x1; x1 = rotl32(x1,(c)); x1 ^= x0;          \
    x0 += x1; x1 = rotl32(x1,(d)); x1 ^= x0;
    TF_R4(13,15,26,6)   x0 += ks1; x1 += ks2 + 1u;
    TF_R4(17,29,16,24)  x0 += ks2; x1 += ks0 + 2u;
    TF_R4(13,15,26,6)   x0 += ks0; x1 += ks1 + 3u;
    TF_R4(17,29,16,24)  x0 += ks1; x1 += ks2 + 4u;
    TF_R4(13,15,26,6)   x0 += ks2; x1 += ks0 + 5u;
#undef TF_R4
    o0 = x0; o1 = x1;
}

// XLA ErfInv float32 polynomial
__device__ __forceinline__ float erfinv_xla(float x) {
    float w = -log1pf(-x * x);
    float p;
    if (w < 5.0f) {
        w -= 2.5f;
        p = 2.81022636e-08f;
        p = fmaf(p, w, 3.43273939e-07f);
        p = fmaf(p, w, -3.5233877e-06f);
        p = fmaf(p, w, -4.39150654e-06f);
        p = fmaf(p, w, 0.00021858087f);
        p = fmaf(p, w, -0.00125372503f);
        p = fmaf(p, w, -0.00417768164f);
        p = fmaf(p, w, 0.246640727f);
        p = fmaf(p, w, 1.50140941f);
    } else {
        w = sqrtf(w) - 3.0f;
        p = -0.000200214257f;
        p = fmaf(p, w, 0.000100950558f);
        p = fmaf(p, w, 0.00134934322f);
        p = fmaf(p, w, -0.00367342844f);
        p = fmaf(p, w, 0.00573950773f);
        p = fmaf(p, w, -0.0076224613f);
        p = fmaf(p, w, 0.00943887047f);
        p = fmaf(p, w, 1.00167406f);
        p = fmaf(p, w, 2.83297682f);
    }
    return p * x;
}

__device__ __forceinline__ float bits_to_normal(uint32_t b) {
    float f = __uint_as_float((b >> 9) | 0x3F800000u) - 1.0f;   // [0,1)
    const float lo = -0.99999994f;                               // nextafter(-1,0)
    const float span = 1.0f - lo;
    float u = fmaf(f, span, lo);
    u = fmaxf(lo, u);
    return 1.41421356f * erfinv_xla(u);   // sqrt(2)
}

// ---------------------------------------------------------------------------
// 1) Generate direction matrices: 4 independent elements per thread (ILP).
//    Also resets the loss accumulator for graph replay.
// ---------------------------------------------------------------------------
__global__ void gen_dirs_kernel() {
    int base = blockIdx.x * 1024 + threadIdx.x;
    if (blockIdx.x == 0 && threadIdx.x == 0) g_loss = 0.0f;
    #pragma unroll
    for (int u = 0; u < 4; u++) {
        int i = base + u * 256;
        if (i < SZ1) {
            uint32_t o0, o1;
            threefry_0_42(0u, (uint32_t)i, o0, o1);
            g_v1[i] = bits_to_normal(o0 ^ o1);
        } else if (i < SZ1 + SZ2) {
            int j = i - SZ1;
            uint32_t o0, o1;
            threefry_0_42(0u, (uint32_t)j, o0, o1);
            g_v2[j] = bits_to_normal(o0 ^ o1);
        }
    }
}

// ---------------------------------------------------------------------------
// 2) nh^T[t][n] = (sum_k X[n,k] V[k,t]) * rsqrt(sum_k V[k,t]^2)
// ---------------------------------------------------------------------------
__global__ void gemm_kernel(const float* __restrict__ s1,
                            const float* __restrict__ s2) {
    int space = blockIdx.z;
    const float* X = space ? s2 : s1;
    const float* V = space ? g_v2 : g_v1;
    float* OUT     = space ? g_nh2 : g_nh1;
    const int D    = space ? D2 : D1;

    int n0 = blockIdx.x * 32;
    int t0 = blockIdx.y * 32;
    int tx = threadIdx.x;
    int ty = threadIdx.y;

    __shared__ float xs[32][33];   // [n][k]
    __shared__ float vs[32][33];   // [k][t]
    __shared__ float nrm[32];
    __shared__ float inv[32];

    if (ty == 0) nrm[tx] = 0.0f;

    float acc  = 0.0f;
    float nsum = 0.0f;
    for (int k0 = 0; k0 < D; k0 += 32) {
        float v = V[(k0 + ty) * TT + (t0 + tx)];
        xs[ty][tx] = X[(n0 + ty) * D + (k0 + tx)];
        vs[ty][tx] = v;
        nsum = fmaf(v, v, nsum);
        __syncthreads();
        #pragma unroll
        for (int k = 0; k < 32; k++)
            acc = fmaf(xs[tx][k], vs[k][ty], acc);
        __syncthreads();
    }
    atomicAdd(&nrm[tx], nsum);
    __syncthreads();
    if (ty == 0) inv[tx] = rsqrtf(nrm[tx]);
    __syncthreads();

    OUT[(t0 + ty) * NN + (n0 + tx)] = acc * inv[ty];
}

// ---------------------------------------------------------------------------
// 3) ECT difference + loss + finalize. One block per direction t.
//    Merged +/- accumulation (space1 +, space2 -): only ect1-ect2 matters.
//    Fixed 7-bin window centered at floor(a) with per-lane predicated atomics
//    (points fully outside [-1,1] contribute only the cnt step, ~free).
//    sigmoid(z) = 0.5 + 0.5*tanh(z/2) via hardware tanh.approx.
// ---------------------------------------------------------------------------
__device__ __forceinline__ float tanh_hw(float x) {
    float y;
    asm("tanh.approx.f32 %0, %1;" : "=f"(y) : "f"(x));
    return y;
}

__global__ void __launch_bounds__(384) ect_loss_kernel(float* __restrict__ out) {
    int t    = blockIdx.x;
    int tid  = threadIdx.x;
    int lane = tid & 31, wid = tid >> 5;   // 12 warps

    __shared__ float acc[RR];
    __shared__ int   cnt[RR];
    __shared__ int   wsum[12];
    __shared__ int   wofs[12];
    __shared__ float ps[12];

    acc[tid] = 0.0f;
    cnt[tid] = 0;
    __syncthreads();

    float nh1 = g_nh1[t * NN + tid];
    float nh2 = g_nh2[t * NN + tid];

    const float AI   = 383.0f / 2.0f;     // 1/H
    const float H250 = 500.0f / 383.0f;   // (z/2) step per bin

    float a1 = (nh1 + 1.0f) * AI;
    float a2 = (nh2 + 1.0f) * AI;
    int ia1 = (int)floorf(a1);
    int ia2 = (int)floorf(a2);

    // step part: all r >= ia+4 get the full +/-1
    int c1 = ia1 + 4; if (c1 < 0) c1 = 0;
    int c2 = ia2 + 4; if (c2 < 0) c2 = 0;
    if (c1 <= RR - 1) atomicAdd(&cnt[c1], 1);
    if (c2 <= RR - 1) atomicAdd(&cnt[c2], -1);

    // smooth window: 7 bins [ia-3, ia+3]
    int   rlo1 = ia1 - 3,                rlo2 = ia2 - 3;
    float b1   = -250.0f * (1.0f + nh1), b2  = -250.0f * (1.0f + nh2);
    #pragma unroll
    for (int i = 0; i < 7; i++) {
        int r1 = rlo1 + i;
        int r2 = rlo2 + i;
        if ((unsigned)r1 < (unsigned)RR) {
            float s = fmaf(0.5f, tanh_hw(fmaf((float)r1, H250, b1)), 0.5f);
            atomicAdd(&acc[r1], s);
        }
        if ((unsigned)r2 < (unsigned)RR) {
            float s = fmaf(0.5f, tanh_hw(fmaf((float)r2, H250, b2)), 0.5f);
            atomicAdd(&acc[r2], -s);
        }
    }
    __syncthreads();

    // inclusive block scan of signed cnt over r = tid
    int v = cnt[tid];
    #pragma unroll
    for (int o = 1; o < 32; o <<= 1) {
        int y = __shfl_up_sync(0xffffffffu, v, o);
        if (lane >= o) v += y;
    }
    if (lane == 31) wsum[wid] = v;
    __syncthreads();
    if (tid < 32) {
        int a = (tid < 12) ? wsum[tid] : 0;
        #pragma unroll
        for (int o = 1; o < 32; o <<= 1) {
            int y = __shfl_up_sync(0xffffffffu, a, o);
            if (tid >= o) a += y;
        }
        if (tid < 12) wofs[tid] = a;
    }
    __syncthreads();
    int pre = v + (wid ? wofs[wid - 1] : 0);

    float d  = acc[tid] + (float)pre;
    float sq = d * d;

    #pragma unroll
    for (int o = 16; o; o >>= 1) sq += __shfl_down_sync(0xffffffffu, sq, o);
    if (lane == 0) ps[wid] = sq;
    __syncthreads();
    if (tid == 0) {
        float s = 0.0f;
        #pragma unroll
        for (int i = 0; i < 12; i++) s += ps[i];
        atomicAdd(&g_loss, s);
        __threadfence();
        unsigned prev = atomicAdd(&g_done, 1u);
        if (prev == (unsigned)(gridDim.x - 1)) {
            g_done = 0u;  // self-reset for graph replay
            float total = *((volatile float*)&g_loss);
            out[0] = total * (1.0f / (float)(RR * TT));
        }
    }
}

extern "C" void kernel_launch(void* const* d_in, const int* in_sizes, int n_in,
                              void* d_out, int out_size) {
    const float* s1 = (const float*)d_in[0];   // [384, 128]
    const float* s2 = (const float*)d_in[1];   // [384, 32]
    float* out = (float*)d_out;

    gen_dirs_kernel<<<60, 256>>>();            // 60*1024 = 61440 elements
    gemm_kernel<<<dim3(NN / 32, TT / 32, 2), dim3(32, 32)>>>(s1, s2);
    ect_loss_kernel<<<TT, NN>>>(out);
}